// round 13
// baseline (speedup 1.0000x reference)
#include <cuda_runtime.h>
#include <cuda_fp16.h>
#include <cstdint>

// MMD loss, single persistent kernel:
//   phase 1: fp16 convert + row norms + colsums (grid-strided)
//   grid barrier (296 blocks == exactly resident)
//   phase 2: single-pass fp16 HMMA pairwise tile GEMM, double-buffered smem,
//            MMA/epilogue interleaved per 16-row strip (pipe overlap)
//   result = (1/4096^2) * sum s_a s_b (u+u^2+u^4+u^8+u^16), u = exp(-L2/(16bw))

#define N_TOTAL 8192
#define HALF_N  4096
#define D       64
#define TILE    128
#define NT      64
#define NTILES  2080
#define GRID_MAIN 296
#define NFULL   2072            // = 296*7 tiles distributed evenly
// 8 leftover tiles -> 32 column-quarter units (128x32) for blocks 0..31

#define ROWB    144             // bytes per smem tile row (72 halfs; 36 words % 32 = 4)
#define TILEB   18432           // 128*144
#define ABUF(b) ((b) * 36864)
#define BBUF(b) ((b) * 36864 + TILEB)
#define NSA_OFF 73728           // float[2][128] (negc * sqA)
#define NSB_OFF 74752           // float[2][128]
#define RED_OFF 75776           // double[256]
#define SMEM_TOTAL 77824

__device__ __half  g_buf[(size_t)N_TOTAL * D];   // fp16 rows
__device__ float  g_sq[N_TOTAL];
__device__ float  g_colsum[D];
__device__ double g_sumsq;
__device__ double g_acc;
__device__ int    g_bar;
__device__ int    g_done;

// ---------------- helpers ----------------
__device__ __forceinline__ uint32_t smem_u32(const void* p) {
    uint32_t a;
    asm("{ .reg .u64 t; cvta.to.shared.u64 t, %1; cvt.u32.u64 %0, t; }" : "=r"(a) : "l"(p));
    return a;
}
__device__ __forceinline__ float ex2f(float x) {
    float y; asm("ex2.approx.ftz.f32 %0, %1;" : "=f"(y) : "f"(x)); return y;
}
__device__ __forceinline__ uint64_t pack2(float lo, float hi) {
    uint64_t r; asm("mov.b64 %0, {%1, %2};" : "=l"(r) : "f"(lo), "f"(hi)); return r;
}
__device__ __forceinline__ void unpack2(uint64_t v, float& lo, float& hi) {
    asm("mov.b64 {%0, %1}, %2;" : "=f"(lo), "=f"(hi) : "l"(v));
}
__device__ __forceinline__ uint64_t fma2(uint64_t a, uint64_t b, uint64_t c) {
    uint64_t d; asm("fma.rn.f32x2 %0, %1, %2, %3;" : "=l"(d) : "l"(a), "l"(b), "l"(c)); return d;
}
__device__ __forceinline__ uint64_t mul2(uint64_t a, uint64_t b) {
    uint64_t d; asm("mul.rn.f32x2 %0, %1, %2;" : "=l"(d) : "l"(a), "l"(b)); return d;
}
__device__ __forceinline__ uint64_t add2(uint64_t a, uint64_t b) {
    uint64_t d; asm("add.rn.f32x2 %0, %1, %2;" : "=l"(d) : "l"(a), "l"(b)); return d;
}
__device__ __forceinline__ void ldsm_x4(uint32_t addr, uint32_t* r) {
    asm volatile("ldmatrix.sync.aligned.m8n8.x4.shared.b16 {%0,%1,%2,%3}, [%4];"
        : "=r"(r[0]), "=r"(r[1]), "=r"(r[2]), "=r"(r[3]) : "r"(addr));
}
__device__ __forceinline__ void mma16816(float* c, const uint32_t* a, uint32_t b0, uint32_t b1) {
    asm volatile(
        "mma.sync.aligned.m16n8k16.row.col.f32.f16.f16.f32 "
        "{%0,%1,%2,%3}, {%4,%5,%6,%7}, {%8,%9}, {%0,%1,%2,%3};"
        : "+f"(c[0]), "+f"(c[1]), "+f"(c[2]), "+f"(c[3])
        : "r"(a[0]), "r"(a[1]), "r"(a[2]), "r"(a[3]), "r"(b0), "r"(b1));
}
__device__ __forceinline__ void cp16(uint32_t saddr, const void* gaddr) {
    asm volatile("cp.async.cg.shared.global [%0], [%1], 16;" :: "r"(saddr), "l"(gaddr));
}

// ---------------- fused MMA + epilogue, interleaved per 16-row strip ----------
// All B fragments register-resident; per strip: 4 A-LDSM, 16 HMMA, 16-cell
// epilogue — tensor/fma/MUFU work co-issuable within one warp.
template<int NI>
__device__ __forceinline__ float tile_work(uint32_t aBase, uint32_t bBase,
                                           const float* nsAb, const float* nsBb,
                                           int lane, int w, uint64_t M2NC) {
    int wr = w >> 2, wc = w & 3;
    int g = lane >> 2, tq = lane & 3;
    uint32_t aAddr = aBase + (uint32_t)((wr * 64 + (lane & 15)) * ROWB)
                   + (uint32_t)(lane >> 4) * 16;
    uint32_t bAddr = bBase
        + (uint32_t)(wc * 8 * NI + ((lane >> 4) << 3) + (lane & 7)) * ROWB
        + (uint32_t)((lane >> 3) & 1) * 16;

    // hoist all B fragments (8 LDSM for NI=4)
    uint32_t bf[4][8];
    #pragma unroll
    for (int ks = 0; ks < 4; ++ks) {
        ldsm_x4(bAddr + (uint32_t)ks * 32, &bf[ks][0]);
        if (NI == 4) ldsm_x4(bAddr + (uint32_t)ks * 32 + 16 * ROWB, &bf[ks][4]);
    }

    uint64_t partp = pack2(0.0f, 0.0f);
    #pragma unroll
    for (int mi = 0; mi < 4; ++mi) {
        float acc[4][4];
        #pragma unroll
        for (int ni = 0; ni < NI; ++ni)
            #pragma unroll
            for (int q = 0; q < 4; ++q) acc[ni][q] = 0.0f;

        #pragma unroll
        for (int ks = 0; ks < 4; ++ks) {
            uint32_t af[4];
            ldsm_x4(aAddr + (uint32_t)ks * 32 + (uint32_t)(mi * 16 * ROWB), af);
            mma16816(acc[0], af, bf[ks][0], bf[ks][1]);
            if (NI >= 2) mma16816(acc[1], af, bf[ks][2], bf[ks][3]);
            if (NI == 4) {
                mma16816(acc[2], af, bf[ks][4], bf[ks][5]);
                mma16816(acc[3], af, bf[ks][6], bf[ks][7]);
            }
        }

        // epilogue chunk for this strip (16 cells/thread for NI=4)
        float na0 = nsAb[wr * 64 + mi * 16 + g];
        float na1 = nsAb[wr * 64 + mi * 16 + g + 8];
        uint64_t na0p = pack2(na0, na0), na1p = pack2(na1, na1);
        #pragma unroll
        for (int ni = 0; ni < NI; ++ni) {
            int cb = wc * 8 * NI + ni * 8 + tq * 2;
            uint64_t nbp = pack2(nsBb[cb], nsBb[cb + 1]);
            #pragma unroll
            for (int h = 0; h < 2; ++h) {
                uint64_t ap = pack2(acc[ni][2 * h], acc[ni][2 * h + 1]);
                uint64_t xp = fma2(ap, M2NC, add2(h ? na1p : na0p, nbp));
                float xl, xh; unpack2(xp, xl, xh);
                uint64_t u  = pack2(ex2f(xl), ex2f(xh));
                uint64_t u2 = mul2(u, u);
                uint64_t u4 = mul2(u2, u2);
                uint64_t u8 = mul2(u4, u4);
                partp = add2(partp, add2(add2(u, u2), add2(u4, u8)));
                partp = fma2(u8, u8, partp);            // + u^16
            }
        }
    }
    float pl, ph; unpack2(partp, pl, ph);
    return pl + ph;
}

// ---------------------------------------------------------------------------
__global__ void __launch_bounds__(256, 2)
k_all(const float* __restrict__ src, const float* __restrict__ tgt,
      float* __restrict__ out) {
    extern __shared__ char smem[];
    uint32_t sbase = smem_u32(smem);
    float*  nsA = (float*)(smem + NSA_OFF);
    float*  nsB = (float*)(smem + NSB_OFF);
    double* red = (double*)(smem + RED_OFF);
    __shared__ float s_negc;

    int t = threadIdx.x, lane = t & 31, w = t >> 5;
    int b = blockIdx.x;

    // ================= phase 1: row preprocessing =================
    {
        float*  sc   = (float*)(smem);
        double* sred = (double*)(smem + 256);
        if (t < D) sc[t] = 0.0f;
        __syncthreads();

        float c0 = 0.0f, c1 = 0.0f, ssq = 0.0f;
        for (int r = b * 8 + w; r < N_TOTAL; r += GRID_MAIN * 8) {
            const float* row = (r < HALF_N) ? src + (size_t)r * D
                                            : tgt + (size_t)(r - HALF_N) * D;
            float2 v = ((const float2*)row)[lane];
            c0 += v.x; c1 += v.y;
            *(__half2*)(g_buf + ((size_t)r << 6) + 2 * lane) =
                __floats2half2_rn(v.x, v.y);
            float s = v.x * v.x + v.y * v.y;
            ssq += s;
            #pragma unroll
            for (int o = 16; o; o >>= 1) s += __shfl_xor_sync(0xffffffffu, s, o);
            if (lane == 0) g_sq[r] = s;
        }
        atomicAdd(&sc[2 * lane],     c0);
        atomicAdd(&sc[2 * lane + 1], c1);
        #pragma unroll
        for (int o = 16; o; o >>= 1) ssq += __shfl_xor_sync(0xffffffffu, ssq, o);
        if (lane == 0) sred[w] = (double)ssq;
        __syncthreads();
        if (t < D) atomicAdd(&g_colsum[t], sc[t]);
        if (t == 0) {
            double s = 0.0;
            #pragma unroll
            for (int i = 0; i < 8; ++i) s += sred[i];
            atomicAdd(&g_sumsq, s);
        }
    }

    // ================= grid barrier (all 296 blocks resident) =================
    __threadfence();
    __syncthreads();
    if (t == 0) {
        atomicAdd(&g_bar, 1);
        while (atomicAdd(&g_bar, 0) < GRID_MAIN) __nanosleep(64);
        __threadfence();
    }
    __syncthreads();

    if (t == 0) {
        double norm2 = 0.0;
        for (int j = 0; j < D; ++j) { double c = (double)g_colsum[j]; norm2 += c * c; }
        double n = (double)N_TOTAL;
        double sumL2 = 2.0 * n * g_sumsq - 2.0 * norm2;
        double bw = sumL2 / (n * n - n) * 0.25;
        s_negc = (float)(-1.4426950408889634 / (16.0 * bw));
    }
    __syncthreads();
    float negc = s_negc;
    uint64_t M2NC = pack2(-2.0f * negc, -2.0f * negc);

    // ================= phase 2: tile loop, double-buffered smem ==============
    int nU = 7 + ((b < 32) ? 1 : 0);        // 32 quarter units for blocks 0..31

    auto decode = [&](int i, int& br, int& bc, int& colBase, int& nB) {
        int u;
        if (i < 7) { u = b + GRID_MAIN * i; colBase = 0;             nB = 128; }
        else       { u = NFULL + (b >> 2);  colBase = (b & 3) * 32;  nB = 32;  }
        int rem = u; br = 0;
        while (rem >= NT - br) { rem -= NT - br; ++br; }
        bc = br + rem;
    };
    auto issue_load = [&](int br, int bRow0, int nB, int buf) {
        #pragma unroll
        for (int it = 0; it < 4; ++it) {
            int idx = it * 256 + t;
            int row = idx >> 3, c = idx & 7;
            cp16(sbase + ABUF(buf) + row * ROWB + c * 16,
                 g_buf + (((size_t)(br * TILE + row)) << 6) + c * 8);
        }
        for (int idx = t; idx < nB * 8; idx += 256) {
            int row = idx >> 3, c = idx & 7;
            cp16(sbase + BBUF(buf) + row * ROWB + c * 16,
                 g_buf + (((size_t)(bRow0 + row)) << 6) + c * 8);
        }
        asm volatile("cp.async.commit_group;");
        if (t < 128)             nsA[buf * 128 + t]       = negc * g_sq[br * TILE + t];
        else if (t - 128 < nB)   nsB[buf * 128 + t - 128] = negc * g_sq[bRow0 + t - 128];
    };

    double acc_d = 0.0;
    int br, bc, colBase, nB;
    decode(0, br, bc, colBase, nB);
    issue_load(br, bc * TILE + colBase, nB, 0);

    for (int i = 0; i < nU; ++i) {
        int cbr = br, cbc = bc;
        asm volatile("cp.async.wait_group 0;" ::: "memory");
        __syncthreads();   // load(i) complete; all warps done with buffer (i+1)&1

        if (i + 1 < nU) {  // prefetch next tile — spans this whole iteration
            decode(i + 1, br, bc, colBase, nB);
            issue_load(br, bc * TILE + colBase, nB, (i + 1) & 1);
        }

        uint32_t aB = sbase + ABUF(i & 1), bB = sbase + BBUF(i & 1);
        const float* nsAb = nsA + (i & 1) * 128;
        const float* nsBb = nsB + (i & 1) * 128;
        float part = (i < 7) ? tile_work<4>(aB, bB, nsAb, nsBb, lane, w, M2NC)
                             : tile_work<1>(aB, bB, nsAb, nsBb, lane, w, M2NC);

        float sA = (cbr < NT / 2) ? 1.0f : -1.0f;
        float sB = (cbc < NT / 2) ? 1.0f : -1.0f;
        float wt = (cbr == cbc) ? 1.0f : 2.0f;
        acc_d += (double)part * (double)(sA * sB * wt);
    }

    // ================= reduction + finalize + replay reset =================
    __syncthreads();
    red[t] = acc_d;
    __syncthreads();
    #pragma unroll
    for (int s = 128; s; s >>= 1) {
        if (t < s) red[t] += red[t + s];
        __syncthreads();
    }
    if (t == 0) {
        atomicAdd(&g_acc, red[0]);
        __threadfence();
        int prev = atomicAdd(&g_done, 1);
        if (prev == GRID_MAIN - 1) {
            __threadfence();
            double total = atomicAdd(&g_acc, 0.0);
            out[0] = (float)(total / ((double)HALF_N * (double)HALF_N));
            // reset for next graph replay
            g_acc = 0.0; g_sumsq = 0.0; g_bar = 0; g_done = 0;
            for (int j = 0; j < D; ++j) g_colsum[j] = 0.0f;
            __threadfence();
        }
    }
}

extern "C" void kernel_launch(void* const* d_in, const int* in_sizes, int n_in,
                              void* d_out, int out_size) {
    const float* src = (const float*)d_in[0];
    const float* tgt = (const float*)d_in[1];
    float* out = (float*)d_out;
    (void)in_sizes; (void)n_in; (void)out_size;

    cudaFuncSetAttribute(k_all, cudaFuncAttributeMaxDynamicSharedMemorySize, SMEM_TOTAL);
    k_all<<<GRID_MAIN, 256, SMEM_TOTAL>>>(src, tgt, out);
}

// round 15
// speedup vs baseline: 1.0857x; 1.0857x over previous
#include <cuda_runtime.h>
#include <cuda_fp16.h>
#include <cstdint>

// MMD loss, single persistent kernel, 3 CTAs/SM:
//   phase 1: fp16 convert + row norms + colsums (grid-strided)
//   grid barrier (444 blocks == exactly resident at occupancy 3)
//   phase 2: single-pass fp16 HMMA pairwise tile GEMM, double-buffered smem,
//            strip-wise MMA+epilogue (16 live accumulators, 80-reg budget)
//   result = (1/4096^2) * sum s_a s_b (u+u^2+u^4+u^8+u^16), u = exp(-L2/(16bw))

#define N_TOTAL 8192
#define HALF_N  4096
#define D       64
#define TILE    128
#define NT      64
#define NTILES  2080
#define GRID_MAIN 444           // 3 per SM on 148 SMs (also resident on 152)
#define NFULL   1776            // = 444*4 tiles distributed evenly
#define NEXTRA  304             // blocks 0..303 take tile 1776+b as a 5th unit

#define ROWB    144             // bytes per smem tile row (72 halfs; 36 words % 32 = 4)
#define TILEB   18432           // 128*144
#define ABUF(b) ((b) * 36864)
#define BBUF(b) ((b) * 36864 + TILEB)
#define NSA_OFF 73728           // float[2][128] (negc * sqA)
#define NSB_OFF 74752           // float[2][128]
// reduction double[256] overlays ABUF(0) after the tile loop
#define SMEM_TOTAL 75776

__device__ __half  g_buf[(size_t)N_TOTAL * D];   // fp16 rows
__device__ float  g_sq[N_TOTAL];
__device__ float  g_colsum[D];
__device__ double g_sumsq;
__device__ double g_acc;
__device__ int    g_bar;
__device__ int    g_done;

// ---------------- helpers ----------------
__device__ __forceinline__ uint32_t smem_u32(const void* p) {
    uint32_t a;
    asm("{ .reg .u64 t; cvta.to.shared.u64 t, %1; cvt.u32.u64 %0, t; }" : "=r"(a) : "l"(p));
    return a;
}
__device__ __forceinline__ float ex2f(float x) {
    float y; asm("ex2.approx.ftz.f32 %0, %1;" : "=f"(y) : "f"(x)); return y;
}
__device__ __forceinline__ uint64_t pack2(float lo, float hi) {
    uint64_t r; asm("mov.b64 %0, {%1, %2};" : "=l"(r) : "f"(lo), "f"(hi)); return r;
}
__device__ __forceinline__ void unpack2(uint64_t v, float& lo, float& hi) {
    asm("mov.b64 {%0, %1}, %2;" : "=f"(lo), "=f"(hi) : "l"(v));
}
__device__ __forceinline__ uint64_t fma2(uint64_t a, uint64_t b, uint64_t c) {
    uint64_t d; asm("fma.rn.f32x2 %0, %1, %2, %3;" : "=l"(d) : "l"(a), "l"(b), "l"(c)); return d;
}
__device__ __forceinline__ uint64_t mul2(uint64_t a, uint64_t b) {
    uint64_t d; asm("mul.rn.f32x2 %0, %1, %2;" : "=l"(d) : "l"(a), "l"(b)); return d;
}
__device__ __forceinline__ uint64_t add2(uint64_t a, uint64_t b) {
    uint64_t d; asm("add.rn.f32x2 %0, %1, %2;" : "=l"(d) : "l"(a), "l"(b)); return d;
}
__device__ __forceinline__ void ldsm_x4(uint32_t addr, uint32_t* r) {
    asm volatile("ldmatrix.sync.aligned.m8n8.x4.shared.b16 {%0,%1,%2,%3}, [%4];"
        : "=r"(r[0]), "=r"(r[1]), "=r"(r[2]), "=r"(r[3]) : "r"(addr));
}
__device__ __forceinline__ void mma16816(float* c, const uint32_t* a, uint32_t b0, uint32_t b1) {
    asm volatile(
        "mma.sync.aligned.m16n8k16.row.col.f32.f16.f16.f32 "
        "{%0,%1,%2,%3}, {%4,%5,%6,%7}, {%8,%9}, {%0,%1,%2,%3};"
        : "+f"(c[0]), "+f"(c[1]), "+f"(c[2]), "+f"(c[3])
        : "r"(a[0]), "r"(a[1]), "r"(a[2]), "r"(a[3]), "r"(b0), "r"(b1));
}
__device__ __forceinline__ void cp16(uint32_t saddr, const void* gaddr) {
    asm volatile("cp.async.cg.shared.global [%0], [%1], 16;" :: "r"(saddr), "l"(gaddr));
}

// ---------------- fused MMA + epilogue, per 16-row strip ----------------------
// 16 live accumulators; B fragments reloaded per strip (keeps regs <= 80).
__device__ __forceinline__ float tile_work(uint32_t aBase, uint32_t bBase,
                                           const float* nsAb, const float* nsBb,
                                           int lane, int w, uint64_t M2NC) {
    int wr = w >> 2, wc = w & 3;
    int g = lane >> 2, tq = lane & 3;
    uint32_t aAddr = aBase + (uint32_t)((wr * 64 + (lane & 15)) * ROWB)
                   + (uint32_t)(lane >> 4) * 16;
    uint32_t bAddr = bBase
        + (uint32_t)(wc * 32 + ((lane >> 4) << 3) + (lane & 7)) * ROWB
        + (uint32_t)((lane >> 3) & 1) * 16;

    uint64_t partp = pack2(0.0f, 0.0f);
    #pragma unroll
    for (int mi = 0; mi < 4; ++mi) {
        float acc[4][4];
        #pragma unroll
        for (int ni = 0; ni < 4; ++ni)
            #pragma unroll
            for (int q = 0; q < 4; ++q) acc[ni][q] = 0.0f;

        #pragma unroll
        for (int ks = 0; ks < 4; ++ks) {
            uint32_t bf[8], af[4];
            ldsm_x4(bAddr + (uint32_t)ks * 32, &bf[0]);
            ldsm_x4(bAddr + (uint32_t)ks * 32 + 16 * ROWB, &bf[4]);
            ldsm_x4(aAddr + (uint32_t)ks * 32 + (uint32_t)(mi * 16 * ROWB), af);
            mma16816(acc[0], af, bf[0], bf[1]);
            mma16816(acc[1], af, bf[2], bf[3]);
            mma16816(acc[2], af, bf[4], bf[5]);
            mma16816(acc[3], af, bf[6], bf[7]);
        }

        // epilogue chunk for this strip (16 cells/thread)
        float na0 = nsAb[wr * 64 + mi * 16 + g];
        float na1 = nsAb[wr * 64 + mi * 16 + g + 8];
        uint64_t na0p = pack2(na0, na0), na1p = pack2(na1, na1);
        #pragma unroll
        for (int ni = 0; ni < 4; ++ni) {
            int cb = wc * 32 + ni * 8 + tq * 2;
            uint64_t nbp = pack2(nsBb[cb], nsBb[cb + 1]);
            #pragma unroll
            for (int h = 0; h < 2; ++h) {
                uint64_t ap = pack2(acc[ni][2 * h], acc[ni][2 * h + 1]);
                uint64_t xp = fma2(ap, M2NC, add2(h ? na1p : na0p, nbp));
                float xl, xh; unpack2(xp, xl, xh);
                uint64_t u  = pack2(ex2f(xl), ex2f(xh));
                uint64_t u2 = mul2(u, u);
                uint64_t u4 = mul2(u2, u2);
                uint64_t u8 = mul2(u4, u4);
                partp = add2(partp, add2(add2(u, u2), add2(u4, u8)));
                partp = fma2(u8, u8, partp);            // + u^16
            }
        }
    }
    float pl, ph; unpack2(partp, pl, ph);
    return pl + ph;
}

// ---------------------------------------------------------------------------
__global__ void __launch_bounds__(256, 3)
k_all(const float* __restrict__ src, const float* __restrict__ tgt,
      float* __restrict__ out) {
    extern __shared__ char smem[];
    uint32_t sbase = smem_u32(smem);
    float*  nsA = (float*)(smem + NSA_OFF);
    float*  nsB = (float*)(smem + NSB_OFF);
    __shared__ float s_negc;

    int t = threadIdx.x, lane = t & 31, w = t >> 5;
    int b = blockIdx.x;

    // ================= phase 1: row preprocessing =================
    {
        float*  sc   = (float*)(smem);
        double* sred = (double*)(smem + 256);
        if (t < D) sc[t] = 0.0f;
        __syncthreads();

        float c0 = 0.0f, c1 = 0.0f, ssq = 0.0f;
        for (int r = b * 8 + w; r < N_TOTAL; r += GRID_MAIN * 8) {
            const float* row = (r < HALF_N) ? src + (size_t)r * D
                                            : tgt + (size_t)(r - HALF_N) * D;
            float2 v = ((const float2*)row)[lane];
            c0 += v.x; c1 += v.y;
            *(__half2*)(g_buf + ((size_t)r << 6) + 2 * lane) =
                __floats2half2_rn(v.x, v.y);
            float s = v.x * v.x + v.y * v.y;
            ssq += s;
            #pragma unroll
            for (int o = 16; o; o >>= 1) s += __shfl_xor_sync(0xffffffffu, s, o);
            if (lane == 0) g_sq[r] = s;
        }
        atomicAdd(&sc[2 * lane],     c0);
        atomicAdd(&sc[2 * lane + 1], c1);
        #pragma unroll
        for (int o = 16; o; o >>= 1) ssq += __shfl_xor_sync(0xffffffffu, ssq, o);
        if (lane == 0) sred[w] = (double)ssq;
        __syncthreads();
        if (t < D) atomicAdd(&g_colsum[t], sc[t]);
        if (t == 0) {
            double s = 0.0;
            #pragma unroll
            for (int i = 0; i < 8; ++i) s += sred[i];
            atomicAdd(&g_sumsq, s);
        }
    }

    // ================= grid barrier (all 444 blocks resident) =================
    __threadfence();
    __syncthreads();
    if (t == 0) {
        atomicAdd(&g_bar, 1);
        while (atomicAdd(&g_bar, 0) < GRID_MAIN) __nanosleep(64);
        __threadfence();
    }
    __syncthreads();

    if (t == 0) {
        double norm2 = 0.0;
        for (int j = 0; j < D; ++j) { double c = (double)g_colsum[j]; norm2 += c * c; }
        double n = (double)N_TOTAL;
        double sumL2 = 2.0 * n * g_sumsq - 2.0 * norm2;
        double bw = sumL2 / (n * n - n) * 0.25;
        s_negc = (float)(-1.4426950408889634 / (16.0 * bw));
    }
    __syncthreads();
    float negc = s_negc;
    uint64_t M2NC = pack2(-2.0f * negc, -2.0f * negc);

    // ================= phase 2: tile loop, double-buffered smem ==============
    int nU = 4 + ((b < NEXTRA) ? 1 : 0);

    auto decode = [&](int i, int& br, int& bc) {
        int u = (i < 4) ? (b + GRID_MAIN * i) : (NFULL + b);
        int rem = u; br = 0;
        while (rem >= NT - br) { rem -= NT - br; ++br; }
        bc = br + rem;
    };
    auto issue_load = [&](int br, int bc, int buf) {
        #pragma unroll
        for (int it = 0; it < 4; ++it) {
            int idx = it * 256 + t;
            int row = idx >> 3, c = idx & 7;
            cp16(sbase + ABUF(buf) + row * ROWB + c * 16,
                 g_buf + (((size_t)(br * TILE + row)) << 6) + c * 8);
        }
        #pragma unroll
        for (int it = 0; it < 4; ++it) {
            int idx = it * 256 + t;
            int row = idx >> 3, c = idx & 7;
            cp16(sbase + BBUF(buf) + row * ROWB + c * 16,
                 g_buf + (((size_t)(bc * TILE + row)) << 6) + c * 8);
        }
        asm volatile("cp.async.commit_group;");
        if (t < 128)  nsA[buf * 128 + t]       = negc * g_sq[br * TILE + t];
        else          nsB[buf * 128 + t - 128] = negc * g_sq[bc * TILE + (t - 128)];
    };

    double acc_d = 0.0;
    int br, bc;
    decode(0, br, bc);
    issue_load(br, bc, 0);

    for (int i = 0; i < nU; ++i) {
        int cbr = br, cbc = bc;
        asm volatile("cp.async.wait_group 0;" ::: "memory");
        __syncthreads();   // load(i) complete; all warps done with buffer (i+1)&1

        if (i + 1 < nU) {  // prefetch next tile — spans this whole iteration
            decode(i + 1, br, bc);
            issue_load(br, bc, (i + 1) & 1);
        }

        uint32_t aB = sbase + ABUF(i & 1), bB = sbase + BBUF(i & 1);
        float part = tile_work(aB, bB, nsA + (i & 1) * 128, nsB + (i & 1) * 128,
                               lane, w, M2NC);

        float sA = (cbr < NT / 2) ? 1.0f : -1.0f;
        float sB = (cbc < NT / 2) ? 1.0f : -1.0f;
        float wt = (cbr == cbc) ? 1.0f : 2.0f;
        acc_d += (double)part * (double)(sA * sB * wt);
    }

    // ================= reduction (overlays A buffer) + finalize ==============
    __syncthreads();
    double* red = (double*)(smem);
    red[t] = acc_d;
    __syncthreads();
    #pragma unroll
    for (int s = 128; s; s >>= 1) {
        if (t < s) red[t] += red[t + s];
        __syncthreads();
    }
    if (t == 0) {
        atomicAdd(&g_acc, red[0]);
        __threadfence();
        int prev = atomicAdd(&g_done, 1);
        if (prev == GRID_MAIN - 1) {
            __threadfence();
            double total = atomicAdd(&g_acc, 0.0);
            out[0] = (float)(total / ((double)HALF_N * (double)HALF_N));
            // reset for next graph replay
            g_acc = 0.0; g_sumsq = 0.0; g_bar = 0; g_done = 0;
            for (int j = 0; j < D; ++j) g_colsum[j] = 0.0f;
            __threadfence();
        }
    }
}

extern "C" void kernel_launch(void* const* d_in, const int* in_sizes, int n_in,
                              void* d_out, int out_size) {
    const float* src = (const float*)d_in[0];
    const float* tgt = (const float*)d_in[1];
    float* out = (float*)d_out;
    (void)in_sizes; (void)n_in; (void)out_size;

    cudaFuncSetAttribute(k_all, cudaFuncAttributeMaxDynamicSharedMemorySize, SMEM_TOTAL);
    k_all<<<GRID_MAIN, 256, SMEM_TOTAL>>>(src, tgt, out);
}